// round 6
// baseline (speedup 1.0000x reference)
#include <cuda_runtime.h>
#include <cuda_bf16.h>
#include <cstdint>

#define N_NODES 100000
#define N_EDGES 800000
#define D 128
#define NTOT (3 * N_NODES)
#define ETOT (3 * N_EDGES)
#define SCAN_BLK 1024
#define SCAN_NB ((NTOT + SCAN_BLK - 1) / SCAN_BLK)   // 293

// Scratch (device globals — allocation-free rule)
__device__ float g_agg[3][N_NODES][D];   // holds TF32 BIT PATTERNS after gather
__device__ float g_h[3][N_NODES][D];     // layer-1 activations (fp32)
__device__ float g_out[3][N_NODES][D];
__device__ int   g_is64;
// Fragment-ordered tf32 weights: [layer][g][chunk8][kstep4][wn2][nt8][lane32][reg2]
__device__ unsigned g_Wfrag[2 * 3 * 32768];

// CSR scratch
__device__ int g_cnt[NTOT];
__device__ int g_rowptr[NTOT + 1];
__device__ int g_cursor[NTOT];
__device__ int g_col[ETOT];
__device__ int g_bsum[SCAN_NB];

// ---------------------------------------------------------------------------
__global__ void detect_idx_kernel(const int* __restrict__ ei_words) {
    if (threadIdx.x == 0 && blockIdx.x == 0) {
        int bad = 0;
        #pragma unroll
        for (int i = 0; i < 64; ++i) bad |= ei_words[2 * i + 1];
        g_is64 = (bad == 0) ? 1 : 0;
    }
}

__device__ __forceinline__ void load_edge(const void* ei_raw, int g, int e,
                                          int& src, int& dst) {
    if (g_is64) {
        const long long* ei = (const long long*)ei_raw;
        long long base = (long long)g * 2 * N_EDGES;
        src = (int)ei[base + e];
        dst = (int)ei[base + N_EDGES + e];
    } else {
        const int* ei = (const int*)ei_raw;
        long long base = (long long)g * 2 * N_EDGES;
        src = ei[base + e];
        dst = ei[base + N_EDGES + e];
    }
}

// ---------------------------------------------------------------------------
// CSR build
// ---------------------------------------------------------------------------
__global__ void count_kernel(const void* __restrict__ ei_raw) {
    long long i = (long long)blockIdx.x * blockDim.x + threadIdx.x;
    if (i >= ETOT) return;
    int g = (int)(i / N_EDGES), e = (int)(i % N_EDGES);
    int src, dst;
    load_edge(ei_raw, g, e, src, dst);
    atomicAdd(&g_cnt[g * N_NODES + dst], 1);
}

__global__ void scan1_kernel() {
    __shared__ int s[SCAN_BLK];
    int idx = blockIdx.x * SCAN_BLK + threadIdx.x;
    int v = (idx < NTOT) ? g_cnt[idx] : 0;
    s[threadIdx.x] = v;
    __syncthreads();
    #pragma unroll
    for (int off = 1; off < SCAN_BLK; off <<= 1) {
        int t = (threadIdx.x >= off) ? s[threadIdx.x - off] : 0;
        __syncthreads();
        s[threadIdx.x] += t;
        __syncthreads();
    }
    if (idx < NTOT) g_rowptr[idx] = s[threadIdx.x] - v;
    if (threadIdx.x == SCAN_BLK - 1) g_bsum[blockIdx.x] = s[SCAN_BLK - 1];
}

__global__ void scan2_kernel() {
    __shared__ int s[512];
    int v = (threadIdx.x < SCAN_NB) ? g_bsum[threadIdx.x] : 0;
    s[threadIdx.x] = v;
    __syncthreads();
    #pragma unroll
    for (int off = 1; off < 512; off <<= 1) {
        int t = (threadIdx.x >= off) ? s[threadIdx.x - off] : 0;
        __syncthreads();
        s[threadIdx.x] += t;
        __syncthreads();
    }
    if (threadIdx.x < SCAN_NB) g_bsum[threadIdx.x] = s[threadIdx.x] - v;
}

__global__ void scan3_kernel() {
    int idx = blockIdx.x * SCAN_BLK + threadIdx.x;
    if (idx < NTOT) {
        int r = g_rowptr[idx] + g_bsum[blockIdx.x];
        g_rowptr[idx] = r;
        g_cursor[idx] = r;
    }
    if (idx == 0) g_rowptr[NTOT] = ETOT;
}

__global__ void fill_kernel(const void* __restrict__ ei_raw) {
    long long i = (long long)blockIdx.x * blockDim.x + threadIdx.x;
    if (i >= ETOT) return;
    int g = (int)(i / N_EDGES), e = (int)(i % N_EDGES);
    int src, dst;
    load_edge(ei_raw, g, e, src, dst);
    int pos = atomicAdd(&g_cursor[g * N_NODES + dst], 1);
    g_col[pos] = src;
}

// ---------------------------------------------------------------------------
__device__ __forceinline__ unsigned f2tf32(float x) {
    unsigned r;
    asm("cvt.rna.tf32.f32 %0, %1;" : "=r"(r) : "f"(x));
    return r;
}

// Fragment-ordered weight preconvert.
// word w: [layer*3+g][chunk][kstep][wn][nt][lane][reg]
// n = wn*64 + nt*8 + (lane>>2); k = chunk*32 + kstep*8 + (lane&3) + 4*reg
// k<128 -> Wl[k][n]; else Wr[k-128][n]
__global__ void wconv_kernel(const float* __restrict__ Wl1, const float* __restrict__ Wr1,
                             const float* __restrict__ Wl2, const float* __restrict__ Wr2) {
    int w = blockIdx.x * blockDim.x + threadIdx.x;   // < 2*3*32768
    int lg    = w >> 15;                             // layer*3+g
    int rem   = w & 32767;
    int chunk = rem >> 12;
    int r2    = rem & 4095;
    int kstep = r2 >> 10;
    int wn    = (r2 >> 9) & 1;
    int nt    = (r2 >> 6) & 7;
    int lane  = (r2 >> 1) & 31;
    int reg   = r2 & 1;

    int layer = lg / 3, g = lg % 3;
    int n = wn * 64 + nt * 8 + (lane >> 2);
    int k = chunk * 32 + kstep * 8 + (lane & 3) + 4 * reg;

    const float* Wl = layer ? Wl2 : Wl1;
    const float* Wr = layer ? Wr2 : Wr1;
    float v = (k < 128) ? Wl[(g * 128 + k) * 128 + n]
                        : Wr[(g * 128 + (k - 128)) * 128 + n];
    g_Wfrag[w] = f2tf32(v);
}

// ---------------------------------------------------------------------------
// Gather aggregation (CSR, no atomics). Emits TF32 BITS (ready for MMA A).
// ---------------------------------------------------------------------------
__global__ void __launch_bounds__(256)
gather_kernel(const float* __restrict__ X, unsigned* __restrict__ aggBits) {
    int widx = blockIdx.x * (blockDim.x >> 5) + (threadIdx.x >> 5);
    int lane = threadIdx.x & 31;
    if (widx >= NTOT) return;

    int g = widx / N_NODES;
    const float4* xg = (const float4*)(X + (size_t)g * N_NODES * D);

    int start = g_rowptr[widx];
    int end   = g_rowptr[widx + 1];

    float4 acc0 = make_float4(0.f, 0.f, 0.f, 0.f);
    float4 acc1 = make_float4(0.f, 0.f, 0.f, 0.f);
    int p = start;
    for (; p + 1 < end; p += 2) {
        int s0 = g_col[p], s1 = g_col[p + 1];
        float4 v0 = xg[(size_t)s0 * 32 + lane];
        float4 v1 = xg[(size_t)s1 * 32 + lane];
        acc0.x += v0.x; acc0.y += v0.y; acc0.z += v0.z; acc0.w += v0.w;
        acc1.x += v1.x; acc1.y += v1.y; acc1.z += v1.z; acc1.w += v1.w;
    }
    if (p < end) {
        int s0 = g_col[p];
        float4 v0 = xg[(size_t)s0 * 32 + lane];
        acc0.x += v0.x; acc0.y += v0.y; acc0.z += v0.z; acc0.w += v0.w;
    }
    acc0.x += acc1.x; acc0.y += acc1.y; acc0.z += acc1.z; acc0.w += acc1.w;

    int deg = end - start;
    float norm = 1.0f / (float)max(deg, 1);
    uint4 ob;
    ob.x = f2tf32(acc0.x * norm);
    ob.y = f2tf32(acc0.y * norm);
    ob.z = f2tf32(acc0.z * norm);
    ob.w = f2tf32(acc0.w * norm);
    ((uint4*)aggBits)[(size_t)widx * 32 + lane] = ob;
}

// ---------------------------------------------------------------------------
// cp.async helpers
// ---------------------------------------------------------------------------
__device__ __forceinline__ void cp_async16(uint32_t dst, const void* src) {
    asm volatile("cp.async.cg.shared.global [%0], [%1], 16;"
                 :: "r"(dst), "l"(src));
}
__device__ __forceinline__ void cp_commit() {
    asm volatile("cp.async.commit_group;");
}
template <int N>
__device__ __forceinline__ void cp_wait() {
    asm volatile("cp.async.wait_group %0;" :: "n"(N));
}

// ---------------------------------------------------------------------------
// Fragment-ordered tf32 SAGEConv.
// Block 256 thr, tile M=128 N=128, K=256 in 8 chunks of 32.
// smem: A frag buf [2][4096]w + B frag buf [2][4096]w = 64 KB.
// A frag word: [kstep][wr][mt]*128 + (unit^swz)*4 + reg
// B frag word: [kstep][wn][nt]*64 + lane*2 + reg
// ---------------------------------------------------------------------------
#define FRAG_WORDS 4096
#define CONV_SMEM (4 * FRAG_WORDS * 4 + 1024)

__device__ __forceinline__ int a_word(int r, int kl) {
    int kstep = kl >> 3, kk = kl & 7;
    int wr = r >> 5, mt = (r >> 4) & 1;
    int unit = (((r & 7) * 4) + (kk & 3)) ^ ((r >> 1) & 3);
    int reg = ((r >> 3) & 1) + 2 * (kk >> 2);
    return ((kstep * 4 + wr) * 2 + mt) * 128 + unit * 4 + reg;
}

__global__ void __launch_bounds__(256, 2)
conv_frag_kernel(const float* __restrict__ Xin,      // [3][N][D] fp32 (x or h)
                 const unsigned* __restrict__ AggBits, // [3][N][D] tf32 bits
                 const float* __restrict__ bl,
                 float* __restrict__ Out,
                 int layer, int relu) {
    extern __shared__ char smem_raw[];
    unsigned* smem = (unsigned*)(((uintptr_t)smem_raw + 1023) & ~(uintptr_t)1023);
    unsigned* Abuf[2] = { smem,                  smem + FRAG_WORDS };
    unsigned* Bbuf[2] = { smem + 2 * FRAG_WORDS, smem + 3 * FRAG_WORDS };

    const int g    = blockIdx.y;
    const int tid  = threadIdx.x;
    const int warp = tid >> 5;
    const int lane = tid & 31;
    const int wm   = warp >> 1;      // 0..3
    const int wn   = warp & 1;       // 0..1
    const int rowBase = blockIdx.x * 128;

    const float*    xg = Xin     + (size_t)g * N_NODES * D;
    const unsigned* ag = AggBits + (size_t)g * N_NODES * D;
    const unsigned* Wf = g_Wfrag + (size_t)(layer * 3 + g) * 32768;

    // staging coords: thread handles row sr, k-half skh (16 k values)
    const int sr  = tid >> 1;
    const int skh = tid & 1;
    int srow = rowBase + sr;
    if (srow >= N_NODES) srow = N_NODES - 1;   // clamp; results unsaved

    uint4 regs[4];

    auto ldgA = [&](int chunk) {
        if (chunk < 4) {
            const unsigned* src = ag + (size_t)srow * D + chunk * 32 + skh * 16;
            #pragma unroll
            for (int q = 0; q < 4; ++q) regs[q] = *(const uint4*)(src + q * 4);
        } else {
            const float* src = xg + (size_t)srow * D + (chunk - 4) * 32 + skh * 16;
            #pragma unroll
            for (int q = 0; q < 4; ++q) {
                float4 v = *(const float4*)(src + q * 4);
                regs[q].x = f2tf32(v.x); regs[q].y = f2tf32(v.y);
                regs[q].z = f2tf32(v.z); regs[q].w = f2tf32(v.w);
            }
        }
    };
    auto stsA = [&](unsigned* Ab) {
        #pragma unroll
        for (int q = 0; q < 4; ++q) {
            const unsigned* rv = (const unsigned*)&regs[q];
            #pragma unroll
            for (int i = 0; i < 4; ++i) {
                int kl = skh * 16 + q * 4 + i;
                Ab[a_word(sr, kl)] = rv[i];
            }
        }
    };
    auto stageB = [&](int chunk, int buf) {
        const unsigned* src = Wf + chunk * FRAG_WORDS + tid * 16;
        uint32_t dst = (uint32_t)__cvta_generic_to_shared(Bbuf[buf] + tid * 16);
        #pragma unroll
        for (int j = 0; j < 4; ++j)
            cp_async16(dst + j * 16, src + j * 4);
    };

    float acc[2][8][4];
    #pragma unroll
    for (int mt = 0; mt < 2; ++mt)
        #pragma unroll
        for (int nt = 0; nt < 8; ++nt)
            #pragma unroll
            for (int i = 0; i < 4; ++i) acc[mt][nt][i] = 0.0f;

    // Prologue
    ldgA(0);
    stsA(Abuf[0]);
    stageB(0, 0); cp_commit();
    ldgA(1);

    const int aswz = (lane ^ ((lane >> 3) & 3)) * 4;

    #pragma unroll 1
    for (int c = 0; c < 8; ++c) {
        __syncthreads();                       // prev compute done; buffers free
        if (c + 1 < 8) {
            stsA(Abuf[(c + 1) & 1]);
            stageB(c + 1, (c + 1) & 1); cp_commit();
        }
        if (c + 2 < 8) ldgA(c + 2);
        if (c + 1 < 8) cp_wait<1>(); else cp_wait<0>();
        __syncthreads();                       // staged data visible

        const unsigned* Ab = Abuf[c & 1];
        const unsigned* Bb = Bbuf[c & 1];

        #pragma unroll
        for (int ks = 0; ks < 4; ++ks) {
            unsigned a[2][4];
            #pragma unroll
            for (int mt = 0; mt < 2; ++mt) {
                const uint4 av = *(const uint4*)(Ab + ((ks * 4 + wm) * 2 + mt) * 128 + aswz);
                a[mt][0] = av.x; a[mt][1] = av.y; a[mt][2] = av.z; a[mt][3] = av.w;
            }
            #pragma unroll
            for (int nt = 0; nt < 8; ++nt) {
                const uint2 bv = *(const uint2*)(Bb + ((ks * 2 + wn) * 8 + nt) * 64 + lane * 2);
                #pragma unroll
                for (int mt = 0; mt < 2; ++mt) {
                    asm volatile(
                        "mma.sync.aligned.m16n8k8.row.col.f32.tf32.tf32.f32 "
                        "{%0,%1,%2,%3}, {%4,%5,%6,%7}, {%8,%9}, {%0,%1,%2,%3};"
                        : "+f"(acc[mt][nt][0]), "+f"(acc[mt][nt][1]),
                          "+f"(acc[mt][nt][2]), "+f"(acc[mt][nt][3])
                        : "r"(a[mt][0]), "r"(a[mt][1]), "r"(a[mt][2]), "r"(a[mt][3]),
                          "r"(bv.x), "r"(bv.y));
                }
            }
        }
    }

    // Epilogue
    const float* bg = bl + (size_t)g * D;
    float* og = Out + (size_t)g * N_NODES * D;

    #pragma unroll
    for (int mt = 0; mt < 2; ++mt) {
        const int r0 = rowBase + wm * 32 + mt * 16 + (lane >> 2);
        const int r1 = r0 + 8;
        #pragma unroll
        for (int nt = 0; nt < 8; ++nt) {
            const int ccol = wn * 64 + nt * 8 + (lane & 3) * 2;
            float2 b = *(const float2*)(bg + ccol);
            float2 o0 = make_float2(acc[mt][nt][0] + b.x, acc[mt][nt][1] + b.y);
            float2 o1 = make_float2(acc[mt][nt][2] + b.x, acc[mt][nt][3] + b.y);
            if (relu) {
                o0.x = fmaxf(o0.x, 0.f); o0.y = fmaxf(o0.y, 0.f);
                o1.x = fmaxf(o1.x, 0.f); o1.y = fmaxf(o1.y, 0.f);
            }
            if (r0 < N_NODES) *(float2*)(og + (size_t)r0 * D + ccol) = o0;
            if (r1 < N_NODES) *(float2*)(og + (size_t)r1 * D + ccol) = o1;
        }
    }
}

// out = O[0] + 0.5*(O[1] + O[2])
__global__ void combine_kernel(const float* __restrict__ O, float* __restrict__ out) {
    long long i = (long long)blockIdx.x * blockDim.x + threadIdx.x;
    const long long nv = (long long)N_NODES * D / 4;
    if (i >= nv) return;
    float4 x0 = ((const float4*)O)[i];
    float4 x1 = ((const float4*)(O + (long long)N_NODES * D))[i];
    float4 x2 = ((const float4*)(O + 2LL * N_NODES * D))[i];
    float4 o;
    o.x = x0.x + 0.5f * (x1.x + x2.x);
    o.y = x0.y + 0.5f * (x1.y + x2.y);
    o.z = x0.z + 0.5f * (x1.z + x2.z);
    o.w = x0.w + 0.5f * (x1.w + x2.w);
    ((float4*)out)[i] = o;
}

extern "C" void kernel_launch(void* const* d_in, const int* in_sizes, int n_in,
                              void* d_out, int out_size) {
    const float* x   = (const float*)d_in[0];
    const void*  ei  = d_in[1];
    const float* Wl1 = (const float*)d_in[2];
    const float* bl1 = (const float*)d_in[3];
    const float* Wr1 = (const float*)d_in[4];
    const float* Wl2 = (const float*)d_in[5];
    const float* bl2 = (const float*)d_in[6];
    const float* Wr2 = (const float*)d_in[7];

    void *agg_p, *h_p, *out_p, *cnt_p;
    cudaGetSymbolAddress(&agg_p, g_agg);
    cudaGetSymbolAddress(&h_p,   g_h);
    cudaGetSymbolAddress(&out_p, g_out);
    cudaGetSymbolAddress(&cnt_p, g_cnt);
    unsigned* aggBits = (unsigned*)agg_p;
    float* h  = (float*)h_p;
    float* ob = (float*)out_p;

    cudaFuncSetAttribute(conv_frag_kernel,
                         cudaFuncAttributeMaxDynamicSharedMemorySize, CONV_SMEM);

    // 0) dtype detect + weight fragment preconvert
    detect_idx_kernel<<<1, 32>>>((const int*)ei);
    wconv_kernel<<<(2 * 3 * 32768) / 256, 256>>>(Wl1, Wr1, Wl2, Wr2);

    // 1) CSR build (shared by both layers)
    cudaMemsetAsync(cnt_p, 0, sizeof(g_cnt));
    const int eblk = 256;
    const int egrid = (ETOT + eblk - 1) / eblk;
    count_kernel<<<egrid, eblk>>>(ei);
    scan1_kernel<<<SCAN_NB, SCAN_BLK>>>();
    scan2_kernel<<<1, 512>>>();
    scan3_kernel<<<SCAN_NB, SCAN_BLK>>>();
    fill_kernel<<<egrid, eblk>>>(ei);

    // 2) layer-1 aggregation (tf32 out)
    const int ggrid = (NTOT * 32 + 255) / 256;
    gather_kernel<<<ggrid, 256>>>(x, aggBits);

    // 3) layer-1 conv + relu -> h
    dim3 cgrid((N_NODES + 127) / 128, 3);
    conv_frag_kernel<<<cgrid, 256, CONV_SMEM>>>(x, aggBits, bl1, h, 0, 1);

    // 4) layer-2 aggregation
    gather_kernel<<<ggrid, 256>>>(h, aggBits);

    // 5) layer-2 conv -> per-graph out
    conv_frag_kernel<<<cgrid, 256, CONV_SMEM>>>(h, aggBits, bl2, ob, 1, 0);

    // 6) combine
    const long long nv = (long long)N_NODES * D / 4;
    combine_kernel<<<(unsigned)((nv + 255) / 256), 256>>>(ob, (float*)d_out);
}

// round 7
// speedup vs baseline: 1.1083x; 1.1083x over previous
#include <cuda_runtime.h>
#include <cuda_bf16.h>
#include <cstdint>

#define N_NODES 100000
#define N_EDGES 800000
#define D 128
#define NTOT (3 * N_NODES)
#define ETOT (3 * N_EDGES)
#define SCAN_BLK 1024
#define SCAN_NB ((NTOT + SCAN_BLK - 1) / SCAN_BLK)   // 293

// Scratch (device globals — allocation-free rule)
__device__ float g_agg[3][N_NODES][D];   // TF32 BIT PATTERNS after gather
__device__ float g_h[3][N_NODES][D];     // layer-1 activations (fp32)
__device__ float g_out[3][N_NODES][D];
__device__ int   g_is64;
// Fragment-ordered tf32 weights: [layer][g][chunk8][kstep4][wn2][nt8][lane32][reg2]
__device__ unsigned g_Wfrag[2 * 3 * 32768];

// CSR scratch
__device__ int g_cnt[NTOT];
__device__ int g_rowptr[NTOT + 1];
__device__ int g_cursor[NTOT];
__device__ int g_col[ETOT];
__device__ int g_bsum[SCAN_NB];

// ---------------------------------------------------------------------------
__global__ void detect_idx_kernel(const int* __restrict__ ei_words) {
    if (threadIdx.x == 0 && blockIdx.x == 0) {
        int bad = 0;
        #pragma unroll
        for (int i = 0; i < 64; ++i) bad |= ei_words[2 * i + 1];
        g_is64 = (bad == 0) ? 1 : 0;
    }
}

__device__ __forceinline__ void load_edge(const void* ei_raw, int g, int e,
                                          int& src, int& dst) {
    if (g_is64) {
        const long long* ei = (const long long*)ei_raw;
        long long base = (long long)g * 2 * N_EDGES;
        src = (int)ei[base + e];
        dst = (int)ei[base + N_EDGES + e];
    } else {
        const int* ei = (const int*)ei_raw;
        long long base = (long long)g * 2 * N_EDGES;
        src = ei[base + e];
        dst = ei[base + N_EDGES + e];
    }
}

// ---------------------------------------------------------------------------
// CSR build
// ---------------------------------------------------------------------------
__global__ void count_kernel(const void* __restrict__ ei_raw) {
    long long i = (long long)blockIdx.x * blockDim.x + threadIdx.x;
    if (i >= ETOT) return;
    int g = (int)(i / N_EDGES), e = (int)(i % N_EDGES);
    int src, dst;
    load_edge(ei_raw, g, e, src, dst);
    atomicAdd(&g_cnt[g * N_NODES + dst], 1);
}

__global__ void scan1_kernel() {
    __shared__ int s[SCAN_BLK];
    int idx = blockIdx.x * SCAN_BLK + threadIdx.x;
    int v = (idx < NTOT) ? g_cnt[idx] : 0;
    s[threadIdx.x] = v;
    __syncthreads();
    #pragma unroll
    for (int off = 1; off < SCAN_BLK; off <<= 1) {
        int t = (threadIdx.x >= off) ? s[threadIdx.x - off] : 0;
        __syncthreads();
        s[threadIdx.x] += t;
        __syncthreads();
    }
    if (idx < NTOT) g_rowptr[idx] = s[threadIdx.x] - v;
    if (threadIdx.x == SCAN_BLK - 1) g_bsum[blockIdx.x] = s[SCAN_BLK - 1];
}

__global__ void scan2_kernel() {
    __shared__ int s[512];
    int v = (threadIdx.x < SCAN_NB) ? g_bsum[threadIdx.x] : 0;
    s[threadIdx.x] = v;
    __syncthreads();
    #pragma unroll
    for (int off = 1; off < 512; off <<= 1) {
        int t = (threadIdx.x >= off) ? s[threadIdx.x - off] : 0;
        __syncthreads();
        s[threadIdx.x] += t;
        __syncthreads();
    }
    if (threadIdx.x < SCAN_NB) g_bsum[threadIdx.x] = s[threadIdx.x] - v;
}

__global__ void scan3_kernel() {
    int idx = blockIdx.x * SCAN_BLK + threadIdx.x;
    if (idx < NTOT) {
        int r = g_rowptr[idx] + g_bsum[blockIdx.x];
        g_rowptr[idx] = r;
        g_cursor[idx] = r;
    }
    if (idx == 0) g_rowptr[NTOT] = ETOT;
}

__global__ void fill_kernel(const void* __restrict__ ei_raw) {
    long long i = (long long)blockIdx.x * blockDim.x + threadIdx.x;
    if (i >= ETOT) return;
    int g = (int)(i / N_EDGES), e = (int)(i % N_EDGES);
    int src, dst;
    load_edge(ei_raw, g, e, src, dst);
    int pos = atomicAdd(&g_cursor[g * N_NODES + dst], 1);
    g_col[pos] = src;
}

// ---------------------------------------------------------------------------
__device__ __forceinline__ unsigned f2tf32(float x) {
    unsigned r;
    asm("cvt.rna.tf32.f32 %0, %1;" : "=r"(r) : "f"(x));
    return r;
}

// Fragment-ordered weight preconvert.
// word w: [layer*3+g][chunk][kstep][wn][nt][lane][reg]
// n = wn*64 + nt*8 + (lane>>2); k = chunk*32 + kstep*8 + (lane&3) + 4*reg
__global__ void wconv_kernel(const float* __restrict__ Wl1, const float* __restrict__ Wr1,
                             const float* __restrict__ Wl2, const float* __restrict__ Wr2) {
    int w = blockIdx.x * blockDim.x + threadIdx.x;   // < 2*3*32768
    int lg    = w >> 15;
    int rem   = w & 32767;
    int chunk = rem >> 12;
    int r2    = rem & 4095;
    int kstep = r2 >> 10;
    int wn    = (r2 >> 9) & 1;
    int nt    = (r2 >> 6) & 7;
    int lane  = (r2 >> 1) & 31;
    int reg   = r2 & 1;

    int layer = lg / 3, g = lg % 3;
    int n = wn * 64 + nt * 8 + (lane >> 2);
    int k = chunk * 32 + kstep * 8 + (lane & 3) + 4 * reg;

    const float* Wl = layer ? Wl2 : Wl1;
    const float* Wr = layer ? Wr2 : Wr1;
    float v = (k < 128) ? Wl[(g * 128 + k) * 128 + n]
                        : Wr[(g * 128 + (k - 128)) * 128 + n];
    g_Wfrag[w] = f2tf32(v);
}

// ---------------------------------------------------------------------------
// Gather aggregation (CSR). Emits TF32 BITS.
// ---------------------------------------------------------------------------
__global__ void __launch_bounds__(256)
gather_kernel(const float* __restrict__ X, unsigned* __restrict__ aggBits) {
    int widx = blockIdx.x * (blockDim.x >> 5) + (threadIdx.x >> 5);
    int lane = threadIdx.x & 31;
    if (widx >= NTOT) return;

    int g = widx / N_NODES;
    const float4* xg = (const float4*)(X + (size_t)g * N_NODES * D);

    int start = g_rowptr[widx];
    int end   = g_rowptr[widx + 1];

    float4 acc0 = make_float4(0.f, 0.f, 0.f, 0.f);
    float4 acc1 = make_float4(0.f, 0.f, 0.f, 0.f);
    int p = start;
    for (; p + 1 < end; p += 2) {
        int s0 = g_col[p], s1 = g_col[p + 1];
        float4 v0 = xg[(size_t)s0 * 32 + lane];
        float4 v1 = xg[(size_t)s1 * 32 + lane];
        acc0.x += v0.x; acc0.y += v0.y; acc0.z += v0.z; acc0.w += v0.w;
        acc1.x += v1.x; acc1.y += v1.y; acc1.z += v1.z; acc1.w += v1.w;
    }
    if (p < end) {
        int s0 = g_col[p];
        float4 v0 = xg[(size_t)s0 * 32 + lane];
        acc0.x += v0.x; acc0.y += v0.y; acc0.z += v0.z; acc0.w += v0.w;
    }
    acc0.x += acc1.x; acc0.y += acc1.y; acc0.z += acc1.z; acc0.w += acc1.w;

    int deg = end - start;
    float norm = 1.0f / (float)max(deg, 1);
    uint4 ob;
    ob.x = f2tf32(acc0.x * norm);
    ob.y = f2tf32(acc0.y * norm);
    ob.z = f2tf32(acc0.z * norm);
    ob.w = f2tf32(acc0.w * norm);
    ((uint4*)aggBits)[(size_t)widx * 32 + lane] = ob;
}

// ---------------------------------------------------------------------------
// cp.async helpers
// ---------------------------------------------------------------------------
__device__ __forceinline__ void cp_async16z(uint32_t dst, const void* src, int bytes) {
    asm volatile("cp.async.cg.shared.global [%0], [%1], 16, %2;"
                 :: "r"(dst), "l"(src), "r"(bytes));
}
__device__ __forceinline__ void cp_async16(uint32_t dst, const void* src) {
    asm volatile("cp.async.cg.shared.global [%0], [%1], 16;"
                 :: "r"(dst), "l"(src));
}
__device__ __forceinline__ void cp_commit() {
    asm volatile("cp.async.commit_group;");
}
template <int N>
__device__ __forceinline__ void cp_wait() {
    asm volatile("cp.async.wait_group %0;" :: "n"(N));
}

// ---------------------------------------------------------------------------
// tf32 SAGEConv (R4 structure + B fragments + bits-A for agg chunks).
// Block 256 thr, tile M=128 N=128, K=256 in 8 chunks of 32, double-buffered.
// smem: As[2][128][36] words + Bfrag[2][4096] words.
// ---------------------------------------------------------------------------
#define AS_STRIDE 36
#define AS_BUF (128 * AS_STRIDE)     // 4608 words
#define WS_BUF 4096                  // fragment words per chunk
#define SMEM_WORDS (2 * AS_BUF + 2 * WS_BUF)

__global__ void __launch_bounds__(256, 2)
conv_tf32_kernel(const float* __restrict__ Xin,        // fp32 x or h
                 const unsigned* __restrict__ AggBits, // tf32 bits
                 const float* __restrict__ bl,
                 float* __restrict__ Out,
                 int layer, int relu) {
    extern __shared__ unsigned smem[];
    unsigned* As = smem;                        // [2][128][36]
    unsigned* Ws = smem + 2 * AS_BUF;           // [2][4096]

    const int g    = blockIdx.y;
    const int tid  = threadIdx.x;
    const int warp = tid >> 5;
    const int lane = tid & 31;
    const int wm   = warp >> 1;
    const int wn   = warp & 1;
    const int rowBase = blockIdx.x * 128;

    const float*    xg = Xin     + (size_t)g * N_NODES * D;
    const unsigned* ag = AggBits + (size_t)g * N_NODES * D;
    const unsigned* Wf = g_Wfrag + (size_t)(layer * 3 + g) * 32768;

    uint32_t As_base = (uint32_t)__cvta_generic_to_shared(As);
    uint32_t Ws_base = (uint32_t)__cvta_generic_to_shared(Ws);

    auto stageA = [&](int chunk, int buf) {
        #pragma unroll
        for (int i = 0; i < 4; ++i) {
            int idx = tid + i * 256;
            int r = idx >> 3, kq = idx & 7;
            int row = rowBase + r;
            const void* src = (chunk < 4)
                ? (const void*)(ag + (size_t)row * D + chunk * 32 + kq * 4)
                : (const void*)(xg + (size_t)row * D + (chunk - 4) * 32 + kq * 4);
            uint32_t dst = As_base + (uint32_t)((buf * AS_BUF + r * AS_STRIDE + kq * 4) * 4);
            cp_async16z(dst, src, (row < N_NODES) ? 16 : 0);
        }
    };
    auto stageB = [&](int chunk, int buf) {
        const unsigned* src = Wf + chunk * WS_BUF + tid * 16;
        uint32_t dst = Ws_base + (uint32_t)((buf * WS_BUF + tid * 16) * 4);
        #pragma unroll
        for (int j = 0; j < 4; ++j)
            cp_async16(dst + j * 16, src + j * 4);
    };

    float acc[2][8][4];
    #pragma unroll
    for (int mt = 0; mt < 2; ++mt)
        #pragma unroll
        for (int nt = 0; nt < 8; ++nt)
            #pragma unroll
            for (int i = 0; i < 4; ++i) acc[mt][nt][i] = 0.0f;

    stageA(0, 0); stageB(0, 0); cp_commit();

    #pragma unroll 1
    for (int c = 0; c < 8; ++c) {
        int buf = c & 1;
        if (c < 7) {
            stageA(c + 1, buf ^ 1); stageB(c + 1, buf ^ 1); cp_commit();
            cp_wait<1>();
        } else {
            cp_wait<0>();
        }
        __syncthreads();

        const unsigned* Ab = As + buf * AS_BUF;
        const uint2*    Bb = (const uint2*)(Ws + buf * WS_BUF);
        const bool bits = (c < 4);

        #pragma unroll
        for (int ks = 0; ks < 4; ++ks) {
            const int k0 = ks * 8;
            const int ac = k0 + (lane & 3);

            unsigned a[2][4];
            #pragma unroll
            for (int mt = 0; mt < 2; ++mt) {
                int ar = wm * 32 + mt * 16 + (lane >> 2);
                if (bits) {
                    a[mt][0] = Ab[ar * AS_STRIDE + ac];
                    a[mt][1] = Ab[(ar + 8) * AS_STRIDE + ac];
                    a[mt][2] = Ab[ar * AS_STRIDE + ac + 4];
                    a[mt][3] = Ab[(ar + 8) * AS_STRIDE + ac + 4];
                } else {
                    a[mt][0] = f2tf32(__uint_as_float(Ab[ar * AS_STRIDE + ac]));
                    a[mt][1] = f2tf32(__uint_as_float(Ab[(ar + 8) * AS_STRIDE + ac]));
                    a[mt][2] = f2tf32(__uint_as_float(Ab[ar * AS_STRIDE + ac + 4]));
                    a[mt][3] = f2tf32(__uint_as_float(Ab[(ar + 8) * AS_STRIDE + ac + 4]));
                }
            }

            #pragma unroll
            for (int nt = 0; nt < 8; ++nt) {
                uint2 bv = Bb[((ks * 2 + wn) * 8 + nt) * 32 + lane];
                #pragma unroll
                for (int mt = 0; mt < 2; ++mt) {
                    asm volatile(
                        "mma.sync.aligned.m16n8k8.row.col.f32.tf32.tf32.f32 "
                        "{%0,%1,%2,%3}, {%4,%5,%6,%7}, {%8,%9}, {%0,%1,%2,%3};"
                        : "+f"(acc[mt][nt][0]), "+f"(acc[mt][nt][1]),
                          "+f"(acc[mt][nt][2]), "+f"(acc[mt][nt][3])
                        : "r"(a[mt][0]), "r"(a[mt][1]), "r"(a[mt][2]), "r"(a[mt][3]),
                          "r"(bv.x), "r"(bv.y));
                }
            }
        }
        __syncthreads();
    }

    // Epilogue
    const float* bg = bl + (size_t)g * D;
    float* og = Out + (size_t)g * N_NODES * D;

    #pragma unroll
    for (int mt = 0; mt < 2; ++mt) {
        const int r0 = rowBase + wm * 32 + mt * 16 + (lane >> 2);
        const int r1 = r0 + 8;
        #pragma unroll
        for (int nt = 0; nt < 8; ++nt) {
            const int ccol = wn * 64 + nt * 8 + (lane & 3) * 2;
            float2 b = *(const float2*)(bg + ccol);
            float2 o0 = make_float2(acc[mt][nt][0] + b.x, acc[mt][nt][1] + b.y);
            float2 o1 = make_float2(acc[mt][nt][2] + b.x, acc[mt][nt][3] + b.y);
            if (relu) {
                o0.x = fmaxf(o0.x, 0.f); o0.y = fmaxf(o0.y, 0.f);
                o1.x = fmaxf(o1.x, 0.f); o1.y = fmaxf(o1.y, 0.f);
            }
            if (r0 < N_NODES) *(float2*)(og + (size_t)r0 * D + ccol) = o0;
            if (r1 < N_NODES) *(float2*)(og + (size_t)r1 * D + ccol) = o1;
        }
    }
}

// out = O[0] + 0.5*(O[1] + O[2])
__global__ void combine_kernel(const float* __restrict__ O, float* __restrict__ out) {
    long long i = (long long)blockIdx.x * blockDim.x + threadIdx.x;
    const long long nv = (long long)N_NODES * D / 4;
    if (i >= nv) return;
    float4 x0 = ((const float4*)O)[i];
    float4 x1 = ((const float4*)(O + (long long)N_NODES * D))[i];
    float4 x2 = ((const float4*)(O + 2LL * N_NODES * D))[i];
    float4 o;
    o.x = x0.x + 0.5f * (x1.x + x2.x);
    o.y = x0.y + 0.5f * (x1.y + x2.y);
    o.z = x0.z + 0.5f * (x1.z + x2.z);
    o.w = x0.w + 0.5f * (x1.w + x2.w);
    ((float4*)out)[i] = o;
}

extern "C" void kernel_launch(void* const* d_in, const int* in_sizes, int n_in,
                              void* d_out, int out_size) {
    const float* x   = (const float*)d_in[0];
    const void*  ei  = d_in[1];
    const float* Wl1 = (const float*)d_in[2];
    const float* bl1 = (const float*)d_in[3];
    const float* Wr1 = (const float*)d_in[4];
    const float* Wl2 = (const float*)d_in[5];
    const float* bl2 = (const float*)d_in[6];
    const float* Wr2 = (const float*)d_in[7];

    void *agg_p, *h_p, *out_p, *cnt_p;
    cudaGetSymbolAddress(&agg_p, g_agg);
    cudaGetSymbolAddress(&h_p,   g_h);
    cudaGetSymbolAddress(&out_p, g_out);
    cudaGetSymbolAddress(&cnt_p, g_cnt);
    unsigned* aggBits = (unsigned*)agg_p;
    float* h  = (float*)h_p;
    float* ob = (float*)out_p;

    cudaFuncSetAttribute(conv_tf32_kernel,
                         cudaFuncAttributeMaxDynamicSharedMemorySize,
                         SMEM_WORDS * 4);

    // 0) dtype detect + weight fragment preconvert
    detect_idx_kernel<<<1, 32>>>((const int*)ei);
    wconv_kernel<<<(2 * 3 * 32768) / 256, 256>>>(Wl1, Wr1, Wl2, Wr2);

    // 1) CSR build (shared by both layers)
    cudaMemsetAsync(cnt_p, 0, sizeof(g_cnt));
    const int eblk = 256;
    const int egrid = (ETOT + eblk - 1) / eblk;
    count_kernel<<<egrid, eblk>>>(ei);
    scan1_kernel<<<SCAN_NB, SCAN_BLK>>>();
    scan2_kernel<<<1, 512>>>();
    scan3_kernel<<<SCAN_NB, SCAN_BLK>>>();
    fill_kernel<<<egrid, eblk>>>(ei);

    // 2) layer-1 aggregation (tf32 bits out)
    const int ggrid = (NTOT * 32 + 255) / 256;
    gather_kernel<<<ggrid, 256>>>(x, aggBits);

    // 3) layer-1 conv + relu -> h
    dim3 cgrid((N_NODES + 127) / 128, 3);
    conv_tf32_kernel<<<cgrid, 256, SMEM_WORDS * 4>>>(x, aggBits, bl1, h, 0, 1);

    // 4) layer-2 aggregation
    gather_kernel<<<ggrid, 256>>>(h, aggBits);

    // 5) layer-2 conv -> per-graph out
    conv_tf32_kernel<<<cgrid, 256, SMEM_WORDS * 4>>>(h, aggBits, bl2, ob, 1, 0);

    // 6) combine
    const long long nv = (long long)N_NODES * D / 4;
    combine_kernel<<<(unsigned)((nv + 255) / 256), 256>>>(ob, (float*)d_out);
}

// round 8
// speedup vs baseline: 1.1826x; 1.0671x over previous
#include <cuda_runtime.h>
#include <cuda_bf16.h>
#include <cstdint>

#define N_NODES 100000
#define N_EDGES 800000
#define D 128
#define NTOT (3 * N_NODES)
#define ETOT (3 * N_EDGES)
#define SCAN_BLK 1024
#define SCAN_NB ((NTOT + SCAN_BLK - 1) / SCAN_BLK)   // 293

// Scratch (device globals — allocation-free rule)
__device__ float g_agg[3][N_NODES][D];   // TF32 BIT PATTERNS after gather
__device__ float g_h[3][N_NODES][D];     // layer-1 activations (fp32)
__device__ float g_out[3][N_NODES][D];
__device__ int   g_is64;
// Preconverted tf32 weights (linear): [layer][g][k=256][n=128]
__device__ unsigned g_Wtf[2 * 3 * 256 * 128];

// CSR scratch
__device__ int g_cnt[NTOT];
__device__ int g_rowptr[NTOT + 1];
__device__ int g_cursor[NTOT];
__device__ int g_col[ETOT];
__device__ int g_bsum[SCAN_NB];

// ---------------------------------------------------------------------------
__global__ void detect_idx_kernel(const int* __restrict__ ei_words) {
    if (threadIdx.x == 0 && blockIdx.x == 0) {
        int bad = 0;
        #pragma unroll
        for (int i = 0; i < 64; ++i) bad |= ei_words[2 * i + 1];
        g_is64 = (bad == 0) ? 1 : 0;
    }
}

__device__ __forceinline__ void load_edge(const void* ei_raw, int g, int e,
                                          int& src, int& dst) {
    if (g_is64) {
        const long long* ei = (const long long*)ei_raw;
        long long base = (long long)g * 2 * N_EDGES;
        src = (int)ei[base + e];
        dst = (int)ei[base + N_EDGES + e];
    } else {
        const int* ei = (const int*)ei_raw;
        long long base = (long long)g * 2 * N_EDGES;
        src = ei[base + e];
        dst = ei[base + N_EDGES + e];
    }
}

// ---------------------------------------------------------------------------
// CSR build: count -> scan -> fill
// ---------------------------------------------------------------------------
__global__ void count_kernel(const void* __restrict__ ei_raw) {
    long long i = (long long)blockIdx.x * blockDim.x + threadIdx.x;
    if (i >= ETOT) return;
    int g = (int)(i / N_EDGES), e = (int)(i % N_EDGES);
    int src, dst;
    load_edge(ei_raw, g, e, src, dst);
    atomicAdd(&g_cnt[g * N_NODES + dst], 1);
}

__global__ void scan1_kernel() {
    __shared__ int s[SCAN_BLK];
    int idx = blockIdx.x * SCAN_BLK + threadIdx.x;
    int v = (idx < NTOT) ? g_cnt[idx] : 0;
    s[threadIdx.x] = v;
    __syncthreads();
    #pragma unroll
    for (int off = 1; off < SCAN_BLK; off <<= 1) {
        int t = (threadIdx.x >= off) ? s[threadIdx.x - off] : 0;
        __syncthreads();
        s[threadIdx.x] += t;
        __syncthreads();
    }
    if (idx < NTOT) g_rowptr[idx] = s[threadIdx.x] - v;
    if (threadIdx.x == SCAN_BLK - 1) g_bsum[blockIdx.x] = s[SCAN_BLK - 1];
}

__global__ void scan2_kernel() {
    __shared__ int s[512];
    int v = (threadIdx.x < SCAN_NB) ? g_bsum[threadIdx.x] : 0;
    s[threadIdx.x] = v;
    __syncthreads();
    #pragma unroll
    for (int off = 1; off < 512; off <<= 1) {
        int t = (threadIdx.x >= off) ? s[threadIdx.x - off] : 0;
        __syncthreads();
        s[threadIdx.x] += t;
        __syncthreads();
    }
    if (threadIdx.x < SCAN_NB) g_bsum[threadIdx.x] = s[threadIdx.x] - v;
}

__global__ void scan3_kernel() {
    int idx = blockIdx.x * SCAN_BLK + threadIdx.x;
    if (idx < NTOT) {
        int r = g_rowptr[idx] + g_bsum[blockIdx.x];
        g_rowptr[idx] = r;
        g_cursor[idx] = r;
    }
    if (idx == 0) g_rowptr[NTOT] = ETOT;
}

__global__ void fill_kernel(const void* __restrict__ ei_raw) {
    long long i = (long long)blockIdx.x * blockDim.x + threadIdx.x;
    if (i >= ETOT) return;
    int g = (int)(i / N_EDGES), e = (int)(i % N_EDGES);
    int src, dst;
    load_edge(ei_raw, g, e, src, dst);
    int pos = atomicAdd(&g_cursor[g * N_NODES + dst], 1);
    g_col[pos] = src;
}

// ---------------------------------------------------------------------------
__device__ __forceinline__ unsigned f2tf32(float x) {
    unsigned r;
    asm("cvt.rna.tf32.f32 %0, %1;" : "=r"(r) : "f"(x));
    return r;
}

// Preconvert weights: g_Wtf[layer][g][k][n] = tf32; k 0..127 = Wl, 128..255 = Wr.
__global__ void wconv_kernel(const float* __restrict__ Wl1, const float* __restrict__ Wr1,
                             const float* __restrict__ Wl2, const float* __restrict__ Wr2) {
    int i = blockIdx.x * blockDim.x + threadIdx.x;   // < 2*3*256*128
    int l   = i / 98304;
    int rem = i - l * 98304;
    int g   = rem / 32768;
    int r2  = rem - g * 32768;
    int k   = r2 >> 7;        // 0..255
    int n   = r2 & 127;       // 0..127
    const float* Wl = l ? Wl2 : Wl1;
    const float* Wr = l ? Wr2 : Wr1;
    float v = (k < 128) ? Wl[(g * 128 + k) * 128 + n]
                        : Wr[(g * 128 + (k - 128)) * 128 + n];
    g_Wtf[i] = f2tf32(v);
}

// ---------------------------------------------------------------------------
// Gather aggregation (CSR, no atomics). Emits TF32 BITS.
// ---------------------------------------------------------------------------
__global__ void __launch_bounds__(256)
gather_kernel(const float* __restrict__ X, unsigned* __restrict__ aggBits) {
    int widx = blockIdx.x * (blockDim.x >> 5) + (threadIdx.x >> 5);
    int lane = threadIdx.x & 31;
    if (widx >= NTOT) return;

    int g = widx / N_NODES;
    const float4* xg = (const float4*)(X + (size_t)g * N_NODES * D);

    int start = g_rowptr[widx];
    int end   = g_rowptr[widx + 1];

    float4 acc0 = make_float4(0.f, 0.f, 0.f, 0.f);
    float4 acc1 = make_float4(0.f, 0.f, 0.f, 0.f);
    int p = start;
    for (; p + 1 < end; p += 2) {
        int s0 = g_col[p], s1 = g_col[p + 1];
        float4 v0 = xg[(size_t)s0 * 32 + lane];
        float4 v1 = xg[(size_t)s1 * 32 + lane];
        acc0.x += v0.x; acc0.y += v0.y; acc0.z += v0.z; acc0.w += v0.w;
        acc1.x += v1.x; acc1.y += v1.y; acc1.z += v1.z; acc1.w += v1.w;
    }
    if (p < end) {
        int s0 = g_col[p];
        float4 v0 = xg[(size_t)s0 * 32 + lane];
        acc0.x += v0.x; acc0.y += v0.y; acc0.z += v0.z; acc0.w += v0.w;
    }
    acc0.x += acc1.x; acc0.y += acc1.y; acc0.z += acc1.z; acc0.w += acc1.w;

    int deg = end - start;
    float norm = 1.0f / (float)max(deg, 1);
    uint4 ob;
    ob.x = f2tf32(acc0.x * norm);
    ob.y = f2tf32(acc0.y * norm);
    ob.z = f2tf32(acc0.z * norm);
    ob.w = f2tf32(acc0.w * norm);
    ((uint4*)aggBits)[(size_t)widx * 32 + lane] = ob;
}

// ---------------------------------------------------------------------------
// cp.async helpers
// ---------------------------------------------------------------------------
__device__ __forceinline__ void cp_async16z(uint32_t dst, const void* src, int bytes) {
    asm volatile("cp.async.cg.shared.global [%0], [%1], 16, %2;"
                 :: "r"(dst), "l"(src), "r"(bytes));
}
__device__ __forceinline__ void cp_async16(uint32_t dst, const void* src) {
    asm volatile("cp.async.cg.shared.global [%0], [%1], 16;"
                 :: "r"(dst), "l"(src));
}
__device__ __forceinline__ void cp_commit() {
    asm volatile("cp.async.commit_group;");
}
template <int N>
__device__ __forceinline__ void cp_wait() {
    asm volatile("cp.async.wait_group %0;" :: "n"(N));
}

// ---------------------------------------------------------------------------
// tf32 SAGEConv (R4 structure; chunks 0-3 consume A bits without CVT).
// Block 256 thr, tile M=128 N=128, K=256 in 8 chunks of 32, double-buffered.
// smem: As[2][128][36] + Ws[2][32][136] words = 71680 B.
// ---------------------------------------------------------------------------
#define AS_STRIDE 36
#define WS_STRIDE 136
#define AS_BUF (128 * AS_STRIDE)       // 4608 words
#define WS_BUF (32 * WS_STRIDE)        // 4352 words
#define SMEM_WORDS (2 * AS_BUF + 2 * WS_BUF)

// One chunk's compute (4 k-steps x 16 MMAs). BITS=1: A already tf32 bits.
#define CONV_CHUNK(Ab, Wb, BITS)                                               \
    _Pragma("unroll")                                                          \
    for (int ks = 0; ks < 4; ++ks) {                                           \
        const int k0 = ks * 8;                                                 \
        const int ac = k0 + (lane & 3);                                        \
        unsigned a[2][4];                                                      \
        _Pragma("unroll")                                                      \
        for (int mt = 0; mt < 2; ++mt) {                                       \
            int ar = wm * 32 + mt * 16 + (lane >> 2);                          \
            unsigned r0 = (Ab)[ar * AS_STRIDE + ac];                           \
            unsigned r1 = (Ab)[(ar + 8) * AS_STRIDE + ac];                     \
            unsigned r2 = (Ab)[ar * AS_STRIDE + ac + 4];                       \
            unsigned r3 = (Ab)[(ar + 8) * AS_STRIDE + ac + 4];                 \
            if (BITS) {                                                        \
                a[mt][0] = r0; a[mt][1] = r1; a[mt][2] = r2; a[mt][3] = r3;    \
            } else {                                                           \
                a[mt][0] = f2tf32(__uint_as_float(r0));                        \
                a[mt][1] = f2tf32(__uint_as_float(r1));                        \
                a[mt][2] = f2tf32(__uint_as_float(r2));                        \
                a[mt][3] = f2tf32(__uint_as_float(r3));                        \
            }                                                                  \
        }                                                                      \
        _Pragma("unroll")                                                      \
        for (int nt = 0; nt < 8; ++nt) {                                       \
            int n0 = wn * 64 + nt * 8 + (lane >> 2);                           \
            unsigned b0 = (Wb)[(k0 + (lane & 3)) * WS_STRIDE + n0];            \
            unsigned b1 = (Wb)[(k0 + (lane & 3) + 4) * WS_STRIDE + n0];        \
            _Pragma("unroll")                                                  \
            for (int mt = 0; mt < 2; ++mt) {                                   \
                asm volatile(                                                  \
                    "mma.sync.aligned.m16n8k8.row.col.f32.tf32.tf32.f32 "     \
                    "{%0,%1,%2,%3}, {%4,%5,%6,%7}, {%8,%9}, {%0,%1,%2,%3};"   \
                    : "+f"(acc[mt][nt][0]), "+f"(acc[mt][nt][1]),              \
                      "+f"(acc[mt][nt][2]), "+f"(acc[mt][nt][3])               \
                    : "r"(a[mt][0]), "r"(a[mt][1]), "r"(a[mt][2]),             \
                      "r"(a[mt][3]), "r"(b0), "r"(b1));                        \
            }                                                                  \
        }                                                                      \
    }

__global__ void __launch_bounds__(256, 2)
conv_tf32_kernel(const float* __restrict__ Xin,        // fp32 x or h
                 const unsigned* __restrict__ AggBits, // tf32 bits
                 const float* __restrict__ bl,
                 float* __restrict__ Out,
                 int layer, int relu) {
    extern __shared__ unsigned smem[];
    unsigned* As = smem;                    // [2][128][36]
    unsigned* Ws = smem + 2 * AS_BUF;       // [2][32][136]

    const int g    = blockIdx.y;
    const int tid  = threadIdx.x;
    const int warp = tid >> 5;
    const int lane = tid & 31;
    const int wm   = warp >> 1;             // 0..3
    const int wn   = warp & 1;              // 0..1
    const int rowBase = blockIdx.x * 128;

    const float*    xg = Xin     + (size_t)g * N_NODES * D;
    const unsigned* ag = AggBits + (size_t)g * N_NODES * D;
    const unsigned* Wtf = g_Wtf + (size_t)(layer * 3 + g) * 256 * 128;

    uint32_t As_base = (uint32_t)__cvta_generic_to_shared(As);
    uint32_t Ws_base = (uint32_t)__cvta_generic_to_shared(Ws);

    auto stageA = [&](int chunk, int buf) {
        #pragma unroll
        for (int i = 0; i < 4; ++i) {
            int idx = tid + i * 256;
            int r = idx >> 3, kq = idx & 7;
            int row = rowBase + r;
            const void* src = (chunk < 4)
                ? (const void*)(ag + (size_t)row * D + chunk * 32 + kq * 4)
                : (const void*)(xg + (size_t)row * D + (chunk - 4) * 32 + kq * 4);
            uint32_t dst = As_base + (uint32_t)((buf * AS_BUF + r * AS_STRIDE + kq * 4) * 4);
            cp_async16z(dst, src, (row < N_NODES) ? 16 : 0);
        }
    };
    auto stageW = [&](int chunk, int buf) {
        const unsigned* Wsrc = Wtf + (size_t)(chunk * 32) * 128;
        #pragma unroll
        for (int i = 0; i < 4; ++i) {
            int idx = tid + i * 256;
            int k = idx >> 5, nq = idx & 31;
            uint32_t dst = Ws_base + (uint32_t)((buf * WS_BUF + k * WS_STRIDE + nq * 4) * 4);
            cp_async16(dst, Wsrc + k * 128 + nq * 4);
        }
    };

    float acc[2][8][4];
    #pragma unroll
    for (int mt = 0; mt < 2; ++mt)
        #pragma unroll
        for (int nt = 0; nt < 8; ++nt)
            #pragma unroll
            for (int i = 0; i < 4; ++i) acc[mt][nt][i] = 0.0f;

    stageA(0, 0); stageW(0, 0); cp_commit();

    // Chunks 0-3: A is tf32 bits (no CVT in loop)
    #pragma unroll 1
    for (int c = 0; c < 4; ++c) {
        int buf = c & 1;
        stageA(c + 1, buf ^ 1); stageW(c + 1, buf ^ 1); cp_commit();
        cp_wait<1>();
        __syncthreads();
        const unsigned* Ab = As + buf * AS_BUF;
        const unsigned* Wb = Ws + buf * WS_BUF;
        CONV_CHUNK(Ab, Wb, 1)
        __syncthreads();
    }

    // Chunks 4-7: A is fp32 (CVT in loop)
    #pragma unroll 1
    for (int c = 4; c < 8; ++c) {
        int buf = c & 1;
        if (c < 7) {
            stageA(c + 1, buf ^ 1); stageW(c + 1, buf ^ 1); cp_commit();
            cp_wait<1>();
        } else {
            cp_wait<0>();
        }
        __syncthreads();
        const unsigned* Ab = As + buf * AS_BUF;
        const unsigned* Wb = Ws + buf * WS_BUF;
        CONV_CHUNK(Ab, Wb, 0)
        __syncthreads();
    }

    // Epilogue
    const float* bg = bl + (size_t)g * D;
    float* og = Out + (size_t)g * N_NODES * D;

    #pragma unroll
    for (int mt = 0; mt < 2; ++mt) {
        const int r0 = rowBase + wm * 32 + mt * 16 + (lane >> 2);
        const int r1 = r0 + 8;
        #pragma unroll
        for (int nt = 0; nt < 8; ++nt) {
            const int ccol = wn * 64 + nt * 8 + (lane & 3) * 2;
            float2 b = *(const float2*)(bg + ccol);
            float2 o0 = make_float2(acc[mt][nt][0] + b.x, acc[mt][nt][1] + b.y);
            float2 o1 = make_float2(acc[mt][nt][2] + b.x, acc[mt][nt][3] + b.y);
            if (relu) {
                o0.x = fmaxf(o0.x, 0.f); o0.y = fmaxf(o0.y, 0.f);
                o1.x = fmaxf(o1.x, 0.f); o1.y = fmaxf(o1.y, 0.f);
            }
            if (r0 < N_NODES) *(float2*)(og + (size_t)r0 * D + ccol) = o0;
            if (r1 < N_NODES) *(float2*)(og + (size_t)r1 * D + ccol) = o1;
        }
    }
}

// out = O[0] + 0.5*(O[1] + O[2])
__global__ void combine_kernel(const float* __restrict__ O, float* __restrict__ out) {
    long long i = (long long)blockIdx.x * blockDim.x + threadIdx.x;
    const long long nv = (long long)N_NODES * D / 4;
    if (i >= nv) return;
    float4 x0 = ((const float4*)O)[i];
    float4 x1 = ((const float4*)(O + (long long)N_NODES * D))[i];
    float4 x2 = ((const float4*)(O + 2LL * N_NODES * D))[i];
    float4 o;
    o.x = x0.x + 0.5f * (x1.x + x2.x);
    o.y = x0.y + 0.5f * (x1.y + x2.y);
    o.z = x0.z + 0.5f * (x1.z + x2.z);
    o.w = x0.w + 0.5f * (x1.w + x2.w);
    ((float4*)out)[i] = o;
}

extern "C" void kernel_launch(void* const* d_in, const int* in_sizes, int n_in,
                              void* d_out, int out_size) {
    const float* x   = (const float*)d_in[0];
    const void*  ei  = d_in[1];
    const float* Wl1 = (const float*)d_in[2];
    const float* bl1 = (const float*)d_in[3];
    const float* Wr1 = (const float*)d_in[4];
    const float* Wl2 = (const float*)d_in[5];
    const float* bl2 = (const float*)d_in[6];
    const float* Wr2 = (const float*)d_in[7];

    void *agg_p, *h_p, *out_p, *cnt_p;
    cudaGetSymbolAddress(&agg_p, g_agg);
    cudaGetSymbolAddress(&h_p,   g_h);
    cudaGetSymbolAddress(&out_p, g_out);
    cudaGetSymbolAddress(&cnt_p, g_cnt);
    unsigned* aggBits = (unsigned*)agg_p;
    float* h  = (float*)h_p;
    float* ob = (float*)out_p;

    cudaFuncSetAttribute(conv_tf32_kernel,
                         cudaFuncAttributeMaxDynamicSharedMemorySize,
                         SMEM_WORDS * 4);

    // 0) dtype detect + weight preconvert
    detect_idx_kernel<<<1, 32>>>((const int*)ei);
    wconv_kernel<<<(2 * 3 * 256 * 128) / 256, 256>>>(Wl1, Wr1, Wl2, Wr2);

    // 1) CSR build (shared by both layers)
    cudaMemsetAsync(cnt_p, 0, sizeof(g_cnt));
    const int eblk = 256;
    const int egrid = (ETOT + eblk - 1) / eblk;
    count_kernel<<<egrid, eblk>>>(ei);
    scan1_kernel<<<SCAN_NB, SCAN_BLK>>>();
    scan2_kernel<<<1, 512>>>();
    scan3_kernel<<<SCAN_NB, SCAN_BLK>>>();
    fill_kernel<<<egrid, eblk>>>(ei);

    // 2) layer-1 aggregation (tf32 bits out)
    const int ggrid = (NTOT * 32 + 255) / 256;
    gather_kernel<<<ggrid, 256>>>(x, aggBits);

    // 3) layer-1 conv + relu -> h
    dim3 cgrid((N_NODES + 127) / 128, 3);
    conv_tf32_kernel<<<cgrid, 256, SMEM_WORDS * 4>>>(x, aggBits, bl1, h, 0, 1);

    // 4) layer-2 aggregation
    gather_kernel<<<ggrid, 256>>>(h, aggBits);

    // 5) layer-2 conv -> per-graph out
    conv_tf32_kernel<<<cgrid, 256, SMEM_WORDS * 4>>>(h, aggBits, bl2, ob, 1, 0);

    // 6) combine
    const long long nv = (long long)N_NODES * D / 4;
    combine_kernel<<<(unsigned)((nv + 255) / 256), 256>>>(ob, (float*)d_out);
}